// round 4
// baseline (speedup 1.0000x reference)
#include <cuda_runtime.h>

#define BB 2
#define KK 33
#define NN 50000
#define EE 800000
#define RR 200
#define DD 64
#define LL 3
#define NROWS (BB*NN)      /* 100000 */
#define NWORDS (NROWS/32)  /* 3125, exact */
#define BATCH_ELEMS (BB*KK*3)  /* 198 */

__device__ __align__(16) float g_x[NROWS*DD];
__device__ __align__(16) float g_agg[NROWS*DD];
__device__ unsigned g_xmask[NWORDS];
__device__ unsigned g_amask[NWORDS];
__device__ float g_query[BB*DD];
__device__ int   g_h0[BB];
__device__ float g_z[DD];
__device__ int   g_zflag;
__device__ int   g_b64;     // 1 if batch buffer is int64, 0 if int32

// ---------------------------------------------------------------------------
// Detect batch dtype. If int64 (little-endian, values in [0,50000)), every
// odd 32-bit word among the first 198 words is a zero high-word. If int32,
// those words are random values in [0,50000) (P(all zero) ~ 0). Only words
// < 198 are read, which is in-bounds for BOTH layouts.
__global__ void k_detect(const int* __restrict__ bw) {
    int is64 = 1;
    for (int i = 1; i < BATCH_ELEMS; i += 2)
        if (bw[i] != 0) { is64 = 0; break; }
    g_b64 = is64;
}

__device__ __forceinline__ int bat(const void* batch, int idx) {
    return g_b64 ? (int)((const long long*)batch)[idx]
                 : ((const int*)batch)[idx];
}
__device__ __forceinline__ int clampi(int v, int hi) {
    return v < 0 ? 0 : (v >= hi ? hi - 1 : v);
}

// ---------------------------------------------------------------------------
// Zero all scratch state. 6.4M floats per array -> 1.6M float4 per array.
__global__ void k_zero() {
    int i = blockIdx.x * blockDim.x + threadIdx.x;   // 6250*256 = 1,600,000
    float4 z = make_float4(0.f, 0.f, 0.f, 0.f);
    ((float4*)g_x)[i]   = z;
    ((float4*)g_agg)[i] = z;
    if (i < NWORDS) { g_xmask[i] = 0u; g_amask[i] = 0u; }
}

// ---------------------------------------------------------------------------
// Read h0/r0 from batch, build query and boundary (x[b,h0] = query).
__global__ void k_setup(const float* __restrict__ rel,
                        const void* __restrict__ batch) {
    int d = threadIdx.x;  // 64 threads
    for (int b = 0; b < BB; b++) {
        int h0 = clampi(bat(batch, (b*KK + 0)*3 + 0), NN);
        int r0 = clampi(bat(batch, (b*KK + 0)*3 + 2), RR);
        float q = rel[((size_t)b*RR + r0)*DD + d];
        g_query[b*DD + d] = q;
        g_x[((size_t)(b*NN + h0))*DD + d] = q;
        if (d == 0) {
            g_h0[b] = h0;
            int row = b*NN + h0;
            atomicOr(&g_xmask[row >> 5], 1u << (row & 31));
        }
    }
}

// ---------------------------------------------------------------------------
// Message + scatter:  agg[b,dst] += x[b,src] * rel[b,etype],
// skipping edges whose src row is provably zero (activity bitmask).
__global__ void k_scatter(const int* __restrict__ edge_index,
                          const int* __restrict__ etype,
                          const float* __restrict__ rel) {
    int e    = blockIdx.x * blockDim.x + threadIdx.x;
    int lane = threadIdx.x & 31;
    int src = 0, a0 = 0, a1 = 0;
    if (e < EE) {
        src = edge_index[e];
        int row0 = src;
        int row1 = NN + src;
        a0 = (g_xmask[row0 >> 5] >> (row0 & 31)) & 1;
        a1 = (g_xmask[row1 >> 5] >> (row1 & 31)) & 1;
    }
    unsigned b0 = __ballot_sync(0xffffffffu, a0);
    unsigned b1 = __ballot_sync(0xffffffffu, a1);
    unsigned act = b0 | b1;
    while (act) {
        int j = __ffs(act) - 1;
        act &= act - 1;
        int ej = __shfl_sync(0xffffffffu, e,   j);
        int sj = __shfl_sync(0xffffffffu, src, j);
        int dj = 0, tj = 0;
        if (lane == j) { dj = edge_index[EE + ej]; tj = etype[ej]; }
        dj = __shfl_sync(0xffffffffu, dj, j);
        tj = __shfl_sync(0xffffffffu, tj, j);
        #pragma unroll
        for (int b = 0; b < BB; b++) {
            unsigned bb = b ? b1 : b0;
            if (!((bb >> j) & 1)) continue;           // uniform across warp
            float2 xv = ((const float2*)g_x)[((size_t)(b*NN + sj))*32 + lane];
            float2 rv = ((const float2*)rel)[((size_t)(b*RR + tj))*32 + lane];
            float* ap = &g_agg[((size_t)(b*NN + dj))*DD + 2*lane];
            atomicAdd(ap,     xv.x * rv.x);
            atomicAdd(ap + 1, xv.y * rv.y);
            if (lane == 0) {
                int row = b*NN + dj;
                atomicOr(&g_amask[row >> 5], 1u << (row & 31));
            }
        }
    }
}

// ---------------------------------------------------------------------------
// z_l = relu(LN(layer_b[l])): the exact update an all-zero row receives.
__global__ void k_zcalc(const float* __restrict__ layer_b,
                        const float* __restrict__ ln_g,
                        const float* __restrict__ ln_b, int l) {
    __shared__ float s[DD];
    __shared__ float red[2];
    __shared__ int   fl;
    int d = threadIdx.x;  // 64
    float v = layer_b[l*DD + d];
    s[d] = v;
    if (d == 0) fl = 0;
    __syncthreads();
    if (d == 0) {
        float su = 0.f, sq = 0.f;
        for (int i = 0; i < DD; i++) { su += s[i]; sq += s[i]*s[i]; }
        float mu = su * (1.f/DD);
        red[0] = mu;
        red[1] = sq * (1.f/DD) - mu*mu;
    }
    __syncthreads();
    float mu = red[0], var = red[1];
    float z = (v - mu) * rsqrtf(var + 1e-5f) * ln_g[l*DD + d] + ln_b[l*DD + d];
    z = fmaxf(z, 0.f);
    g_z[d] = z;
    if (z != 0.f) atomicOr(&fl, 1);
    __syncthreads();
    if (d == 0) g_zflag = fl;
}

// ---------------------------------------------------------------------------
// Per-row update: upd = relu(LN([agg+boundary, x] @ W_l + b_l)); x += upd.
// One warp owns one 32-row mask word; processes only active rows; re-zeroes
// the agg rows it consumed and clears its amask word.
__global__ void k_update(const float* __restrict__ W,
                         const float* __restrict__ bl,
                         const float* __restrict__ gg,
                         const float* __restrict__ beta, int l) {
    int wid  = (blockIdx.x * blockDim.x + threadIdx.x) >> 5;
    int lane = threadIdx.x & 31;
    if (wid >= NWORDS) return;
    unsigned xm = g_xmask[wid];
    unsigned am = g_amask[wid];
    unsigned act = xm | am;
    if (act) {
        const float* Wl = W + (size_t)l * 2 * DD * DD;
        float bj0  = bl[l*DD + 2*lane],   bj1  = bl[l*DD + 2*lane + 1];
        float gj0  = gg[l*DD + 2*lane],   gj1  = gg[l*DD + 2*lane + 1];
        float btj0 = beta[l*DD + 2*lane], btj1 = beta[l*DD + 2*lane + 1];
        unsigned rem = act;
        while (rem) {
            int jb = __ffs(rem) - 1;
            rem &= rem - 1;
            int row = wid * 32 + jb;
            int b   = row / NN;
            int n   = row - b * NN;
            float2 a2 = ((float2*)g_agg)[(size_t)row*32 + lane];
            float2 x2 = ((float2*)g_x)[(size_t)row*32 + lane];
            if (n == g_h0[b]) {
                a2.x += g_query[b*DD + 2*lane];
                a2.y += g_query[b*DD + 2*lane + 1];
            }
            float acc0 = bj0, acc1 = bj1;
            // cat[0:64] = agg
            #pragma unroll 8
            for (int ii = 0; ii < 32; ii++) {
                float cx = __shfl_sync(0xffffffffu, a2.x, ii);
                float cy = __shfl_sync(0xffffffffu, a2.y, ii);
                float2 w0 = ((const float2*)(Wl + (2*ii    )*DD))[lane];
                float2 w1 = ((const float2*)(Wl + (2*ii + 1)*DD))[lane];
                acc0 += cx*w0.x + cy*w1.x;
                acc1 += cx*w0.y + cy*w1.y;
            }
            // cat[64:128] = x
            #pragma unroll 8
            for (int ii = 0; ii < 32; ii++) {
                float cx = __shfl_sync(0xffffffffu, x2.x, ii);
                float cy = __shfl_sync(0xffffffffu, x2.y, ii);
                float2 w0 = ((const float2*)(Wl + (64 + 2*ii    )*DD))[lane];
                float2 w1 = ((const float2*)(Wl + (64 + 2*ii + 1)*DD))[lane];
                acc0 += cx*w0.x + cy*w1.x;
                acc1 += cx*w0.y + cy*w1.y;
            }
            // LayerNorm over the 64 outputs (2 per lane)
            float su = acc0 + acc1;
            float sq = acc0*acc0 + acc1*acc1;
            #pragma unroll
            for (int o = 16; o; o >>= 1) {
                su += __shfl_xor_sync(0xffffffffu, su, o);
                sq += __shfl_xor_sync(0xffffffffu, sq, o);
            }
            float mu  = su * (1.f/DD);
            float var = sq * (1.f/DD) - mu*mu;
            float rs  = rsqrtf(var + 1e-5f);
            float u0 = fmaxf((acc0 - mu)*rs*gj0 + btj0, 0.f);
            float u1 = fmaxf((acc1 - mu)*rs*gj1 + btj1, 0.f);
            x2.x += u0; x2.y += u1;
            ((float2*)g_x)[(size_t)row*32 + lane] = x2;
            ((float2*)g_agg)[(size_t)row*32 + lane] = make_float2(0.f, 0.f);
        }
        if (lane == 0) g_xmask[wid] = act;  // processed rows may now be nonzero
    }
    if (lane == 0) g_amask[wid] = 0u;       // restore agg invariant
}

// ---------------------------------------------------------------------------
// If z_l != 0, every unprocessed (all-zero) row gets x += z_l. In practice
// z_l == 0 and this is a flag-check no-op.
__global__ void k_fixup() {
    if (g_zflag == 0) return;
    int r = blockIdx.x * blockDim.x + threadIdx.x;
    if (r >= NROWS) return;
    if ((g_xmask[r >> 5] >> (r & 31)) & 1) return;
    for (int d = 0; d < DD; d++) g_x[(size_t)r*DD + d] += g_z[d];
    atomicOr(&g_xmask[r >> 5], 1u << (r & 31));
}

// ---------------------------------------------------------------------------
// Final MLP scoring over the (b,k) query tails.
__global__ void k_score(const void* __restrict__ batch,
                        const float* __restrict__ w1,
                        const float* __restrict__ b1,
                        const float* __restrict__ w2,
                        const float* __restrict__ b2,
                        float* __restrict__ out) {
    __shared__ float feat[2*DD];
    __shared__ float hs[DD];
    int bk = blockIdx.x;            // 0..65
    int b = bk / KK, k = bk % KK;
    int j = threadIdx.x;            // 64
    int t = clampi(bat(batch, (b*KK + k)*3 + 1), NN);
    feat[j]      = g_x[((size_t)(b*NN + t))*DD + j];
    feat[DD + j] = g_query[b*DD + j];
    __syncthreads();
    float acc = b1[j];
    #pragma unroll 8
    for (int i = 0; i < 2*DD; i++) acc += feat[i] * w1[i*DD + j];
    float h = fmaxf(acc, 0.f);
    hs[j] = h * w2[j];
    __syncthreads();
    if (j == 0) {
        float s = b2[0];
        for (int i = 0; i < DD; i++) s += hs[i];
        out[b*KK + k] = s;
    }
}

// ---------------------------------------------------------------------------
extern "C" void kernel_launch(void* const* d_in, const int* in_sizes, int n_in,
                              void* d_out, int out_size) {
    const float* rel      = (const float*)d_in[0];
    const float* layer_w  = (const float*)d_in[1];
    const float* layer_b  = (const float*)d_in[2];
    const float* ln_g     = (const float*)d_in[3];
    const float* ln_b     = (const float*)d_in[4];
    const float* mlp_w1   = (const float*)d_in[5];
    const float* mlp_b1   = (const float*)d_in[6];
    const float* mlp_w2   = (const float*)d_in[7];
    const float* mlp_b2   = (const float*)d_in[8];
    const void*  batch    = d_in[9];
    const int*   edge_idx = (const int*)d_in[10];
    const int*   edge_typ = (const int*)d_in[11];
    float*       out      = (float*)d_out;

    k_detect<<<1, 1>>>((const int*)batch);
    k_zero<<<6250, 256>>>();
    k_setup<<<1, 64>>>(rel, batch);
    for (int l = 0; l < LL; l++) {
        k_scatter<<<(EE + 255)/256, 256>>>(edge_idx, edge_typ, rel);
        k_zcalc<<<1, 64>>>(layer_b, ln_g, ln_b, l);
        k_update<<<(NWORDS*32 + 255)/256, 256>>>(layer_w, layer_b, ln_g, ln_b, l);
        k_fixup<<<(NROWS + 255)/256, 256>>>();
    }
    k_score<<<66, 64>>>(batch, mlp_w1, mlp_b1, mlp_w2, mlp_b2, out);
}

// round 5
// speedup vs baseline: 1.0023x; 1.0023x over previous
#include <cuda_runtime.h>

#define BB 2
#define KK 33
#define NN 50000
#define EE 800000
#define RR 200
#define DD 64
#define LL 3
#define NROWS (BB*NN)      /* 100000 */
#define NWORDS (NROWS/32)  /* 3125, exact */
#define BATCH_ELEMS (BB*KK*3)  /* 198 */

__device__ __align__(16) float g_x[NROWS*DD];
__device__ __align__(16) float g_agg[NROWS*DD];
__device__ unsigned g_xmask[NWORDS];
__device__ unsigned g_amask[NWORDS];
__device__ float g_query[BB*DD];
__device__ int   g_h0[BB];
__device__ float g_z[DD];
__device__ int   g_zflag;
__device__ int   g_b64;     // 1 if batch buffer is int64, 0 if int32

// ---------------------------------------------------------------------------
// Detect batch dtype. If int64 (little-endian, values in [0,50000)), every
// odd 32-bit word among the first 198 words is a zero high-word. If int32,
// those words are random values in [0,50000) (P(all zero) ~ 0). Only words
// < 198 are read, which is in-bounds for BOTH layouts.
__global__ void k_detect(const int* __restrict__ bw) {
    int is64 = 1;
    for (int i = 1; i < BATCH_ELEMS; i += 2)
        if (bw[i] != 0) { is64 = 0; break; }
    g_b64 = is64;
}

__device__ __forceinline__ int bat(const void* batch, int idx) {
    return g_b64 ? (int)((const long long*)batch)[idx]
                 : ((const int*)batch)[idx];
}
__device__ __forceinline__ int clampi(int v, int hi) {
    return v < 0 ? 0 : (v >= hi ? hi - 1 : v);
}

// ---------------------------------------------------------------------------
// Zero all scratch state. 6.4M floats per array -> 1.6M float4 per array.
__global__ void k_zero() {
    int i = blockIdx.x * blockDim.x + threadIdx.x;   // 6250*256 = 1,600,000
    float4 z = make_float4(0.f, 0.f, 0.f, 0.f);
    ((float4*)g_x)[i]   = z;
    ((float4*)g_agg)[i] = z;
    if (i < NWORDS) { g_xmask[i] = 0u; g_amask[i] = 0u; }
}

// ---------------------------------------------------------------------------
// Read h0/r0 from batch, build query and boundary (x[b,h0] = query).
__global__ void k_setup(const float* __restrict__ rel,
                        const void* __restrict__ batch) {
    int d = threadIdx.x;  // 64 threads
    for (int b = 0; b < BB; b++) {
        int h0 = clampi(bat(batch, (b*KK + 0)*3 + 0), NN);
        int r0 = clampi(bat(batch, (b*KK + 0)*3 + 2), RR);
        float q = rel[((size_t)b*RR + r0)*DD + d];
        g_query[b*DD + d] = q;
        g_x[((size_t)(b*NN + h0))*DD + d] = q;
        if (d == 0) {
            g_h0[b] = h0;
            int row = b*NN + h0;
            atomicOr(&g_xmask[row >> 5], 1u << (row & 31));
        }
    }
}

// ---------------------------------------------------------------------------
// Message + scatter:  agg[b,dst] += x[b,src] * rel[b,etype],
// skipping edges whose src row is provably zero (activity bitmask).
__global__ void k_scatter(const int* __restrict__ edge_index,
                          const int* __restrict__ etype,
                          const float* __restrict__ rel) {
    int e    = blockIdx.x * blockDim.x + threadIdx.x;
    int lane = threadIdx.x & 31;
    int src = 0, a0 = 0, a1 = 0;
    if (e < EE) {
        src = edge_index[e];
        int row0 = src;
        int row1 = NN + src;
        a0 = (g_xmask[row0 >> 5] >> (row0 & 31)) & 1;
        a1 = (g_xmask[row1 >> 5] >> (row1 & 31)) & 1;
    }
    unsigned b0 = __ballot_sync(0xffffffffu, a0);
    unsigned b1 = __ballot_sync(0xffffffffu, a1);
    unsigned act = b0 | b1;
    while (act) {
        int j = __ffs(act) - 1;
        act &= act - 1;
        int ej = __shfl_sync(0xffffffffu, e,   j);
        int sj = __shfl_sync(0xffffffffu, src, j);
        int dj = 0, tj = 0;
        if (lane == j) { dj = edge_index[EE + ej]; tj = etype[ej]; }
        dj = __shfl_sync(0xffffffffu, dj, j);
        tj = __shfl_sync(0xffffffffu, tj, j);
        #pragma unroll
        for (int b = 0; b < BB; b++) {
            unsigned bb = b ? b1 : b0;
            if (!((bb >> j) & 1)) continue;           // uniform across warp
            float2 xv = ((const float2*)g_x)[((size_t)(b*NN + sj))*32 + lane];
            float2 rv = ((const float2*)rel)[((size_t)(b*RR + tj))*32 + lane];
            float* ap = &g_agg[((size_t)(b*NN + dj))*DD + 2*lane];
            atomicAdd(ap,     xv.x * rv.x);
            atomicAdd(ap + 1, xv.y * rv.y);
            if (lane == 0) {
                int row = b*NN + dj;
                atomicOr(&g_amask[row >> 5], 1u << (row & 31));
            }
        }
    }
}

// ---------------------------------------------------------------------------
// z_l = relu(LN(layer_b[l])): the exact update an all-zero row receives.
__global__ void k_zcalc(const float* __restrict__ layer_b,
                        const float* __restrict__ ln_g,
                        const float* __restrict__ ln_b, int l) {
    __shared__ float s[DD];
    __shared__ float red[2];
    __shared__ int   fl;
    int d = threadIdx.x;  // 64
    float v = layer_b[l*DD + d];
    s[d] = v;
    if (d == 0) fl = 0;
    __syncthreads();
    if (d == 0) {
        float su = 0.f, sq = 0.f;
        for (int i = 0; i < DD; i++) { su += s[i]; sq += s[i]*s[i]; }
        float mu = su * (1.f/DD);
        red[0] = mu;
        red[1] = sq * (1.f/DD) - mu*mu;
    }
    __syncthreads();
    float mu = red[0], var = red[1];
    float z = (v - mu) * rsqrtf(var + 1e-5f) * ln_g[l*DD + d] + ln_b[l*DD + d];
    z = fmaxf(z, 0.f);
    g_z[d] = z;
    if (z != 0.f) atomicOr(&fl, 1);
    __syncthreads();
    if (d == 0) g_zflag = fl;
}

// ---------------------------------------------------------------------------
// Per-row update: upd = relu(LN([agg+boundary, x] @ W_l + b_l)); x += upd.
// One warp owns one 32-row mask word; processes only active rows; re-zeroes
// the agg rows it consumed and clears its amask word.
__global__ void k_update(const float* __restrict__ W,
                         const float* __restrict__ bl,
                         const float* __restrict__ gg,
                         const float* __restrict__ beta, int l) {
    int wid  = (blockIdx.x * blockDim.x + threadIdx.x) >> 5;
    int lane = threadIdx.x & 31;
    if (wid >= NWORDS) return;
    unsigned xm = g_xmask[wid];
    unsigned am = g_amask[wid];
    unsigned act = xm | am;
    if (act) {
        const float* Wl = W + (size_t)l * 2 * DD * DD;
        float bj0  = bl[l*DD + 2*lane],   bj1  = bl[l*DD + 2*lane + 1];
        float gj0  = gg[l*DD + 2*lane],   gj1  = gg[l*DD + 2*lane + 1];
        float btj0 = beta[l*DD + 2*lane], btj1 = beta[l*DD + 2*lane + 1];
        unsigned rem = act;
        while (rem) {
            int jb = __ffs(rem) - 1;
            rem &= rem - 1;
            int row = wid * 32 + jb;
            int b   = row / NN;
            int n   = row - b * NN;
            float2 a2 = ((float2*)g_agg)[(size_t)row*32 + lane];
            float2 x2 = ((float2*)g_x)[(size_t)row*32 + lane];
            if (n == g_h0[b]) {
                a2.x += g_query[b*DD + 2*lane];
                a2.y += g_query[b*DD + 2*lane + 1];
            }
            float acc0 = bj0, acc1 = bj1;
            // cat[0:64] = agg
            #pragma unroll 8
            for (int ii = 0; ii < 32; ii++) {
                float cx = __shfl_sync(0xffffffffu, a2.x, ii);
                float cy = __shfl_sync(0xffffffffu, a2.y, ii);
                float2 w0 = ((const float2*)(Wl + (2*ii    )*DD))[lane];
                float2 w1 = ((const float2*)(Wl + (2*ii + 1)*DD))[lane];
                acc0 += cx*w0.x + cy*w1.x;
                acc1 += cx*w0.y + cy*w1.y;
            }
            // cat[64:128] = x
            #pragma unroll 8
            for (int ii = 0; ii < 32; ii++) {
                float cx = __shfl_sync(0xffffffffu, x2.x, ii);
                float cy = __shfl_sync(0xffffffffu, x2.y, ii);
                float2 w0 = ((const float2*)(Wl + (64 + 2*ii    )*DD))[lane];
                float2 w1 = ((const float2*)(Wl + (64 + 2*ii + 1)*DD))[lane];
                acc0 += cx*w0.x + cy*w1.x;
                acc1 += cx*w0.y + cy*w1.y;
            }
            // LayerNorm over the 64 outputs (2 per lane)
            float su = acc0 + acc1;
            float sq = acc0*acc0 + acc1*acc1;
            #pragma unroll
            for (int o = 16; o; o >>= 1) {
                su += __shfl_xor_sync(0xffffffffu, su, o);
                sq += __shfl_xor_sync(0xffffffffu, sq, o);
            }
            float mu  = su * (1.f/DD);
            float var = sq * (1.f/DD) - mu*mu;
            float rs  = rsqrtf(var + 1e-5f);
            float u0 = fmaxf((acc0 - mu)*rs*gj0 + btj0, 0.f);
            float u1 = fmaxf((acc1 - mu)*rs*gj1 + btj1, 0.f);
            x2.x += u0; x2.y += u1;
            ((float2*)g_x)[(size_t)row*32 + lane] = x2;
            ((float2*)g_agg)[(size_t)row*32 + lane] = make_float2(0.f, 0.f);
        }
        if (lane == 0) g_xmask[wid] = act;  // processed rows may now be nonzero
    }
    if (lane == 0) g_amask[wid] = 0u;       // restore agg invariant
}

// ---------------------------------------------------------------------------
// If z_l != 0, every unprocessed (all-zero) row gets x += z_l. In practice
// z_l == 0 and this is a flag-check no-op.
__global__ void k_fixup() {
    if (g_zflag == 0) return;
    int r = blockIdx.x * blockDim.x + threadIdx.x;
    if (r >= NROWS) return;
    if ((g_xmask[r >> 5] >> (r & 31)) & 1) return;
    for (int d = 0; d < DD; d++) g_x[(size_t)r*DD + d] += g_z[d];
    atomicOr(&g_xmask[r >> 5], 1u << (r & 31));
}

// ---------------------------------------------------------------------------
// Final MLP scoring over the (b,k) query tails.
__global__ void k_score(const void* __restrict__ batch,
                        const float* __restrict__ w1,
                        const float* __restrict__ b1,
                        const float* __restrict__ w2,
                        const float* __restrict__ b2,
                        float* __restrict__ out) {
    __shared__ float feat[2*DD];
    __shared__ float hs[DD];
    int bk = blockIdx.x;            // 0..65
    int b = bk / KK, k = bk % KK;
    int j = threadIdx.x;            // 64
    int t = clampi(bat(batch, (b*KK + k)*3 + 1), NN);
    feat[j]      = g_x[((size_t)(b*NN + t))*DD + j];
    feat[DD + j] = g_query[b*DD + j];
    __syncthreads();
    float acc = b1[j];
    #pragma unroll 8
    for (int i = 0; i < 2*DD; i++) acc += feat[i] * w1[i*DD + j];
    float h = fmaxf(acc, 0.f);
    hs[j] = h * w2[j];
    __syncthreads();
    if (j == 0) {
        float s = b2[0];
        for (int i = 0; i < DD; i++) s += hs[i];
        out[b*KK + k] = s;
    }
}

// ---------------------------------------------------------------------------
extern "C" void kernel_launch(void* const* d_in, const int* in_sizes, int n_in,
                              void* d_out, int out_size) {
    const float* rel      = (const float*)d_in[0];
    const float* layer_w  = (const float*)d_in[1];
    const float* layer_b  = (const float*)d_in[2];
    const float* ln_g     = (const float*)d_in[3];
    const float* ln_b     = (const float*)d_in[4];
    const float* mlp_w1   = (const float*)d_in[5];
    const float* mlp_b1   = (const float*)d_in[6];
    const float* mlp_w2   = (const float*)d_in[7];
    const float* mlp_b2   = (const float*)d_in[8];
    const void*  batch    = d_in[9];
    const int*   edge_idx = (const int*)d_in[10];
    const int*   edge_typ = (const int*)d_in[11];
    float*       out      = (float*)d_out;

    k_detect<<<1, 1>>>((const int*)batch);
    k_zero<<<6250, 256>>>();
    k_setup<<<1, 64>>>(rel, batch);
    for (int l = 0; l < LL; l++) {
        k_scatter<<<(EE + 255)/256, 256>>>(edge_idx, edge_typ, rel);
        k_zcalc<<<1, 64>>>(layer_b, ln_g, ln_b, l);
        k_update<<<(NWORDS*32 + 255)/256, 256>>>(layer_w, layer_b, ln_g, ln_b, l);
        k_fixup<<<(NROWS + 255)/256, 256>>>();
    }
    k_score<<<66, 64>>>(batch, mlp_w1, mlp_b1, mlp_w2, mlp_b2, out);
}

// round 6
// speedup vs baseline: 1.0687x; 1.0663x over previous
#include <cuda_runtime.h>

#define BB 2
#define KK 33
#define NN 50000
#define EE 800000
#define RR 200
#define DD 64
#define LL 3
#define NROWS (BB*NN)          /* 100000 */
#define NWORDS (NROWS/32)      /* 3125, exact */
#define TABW (NN*2/32)         /* 3125: 2 activity bits per node */
#define BATCH_ELEMS (BB*KK*3)  /* 198 */

__device__ __align__(16) float g_x[NROWS*DD];
__device__ __align__(16) float g_agg[NROWS*DD];   // invariant: zero at launch entry
__device__ unsigned g_xmask[NWORDS];
__device__ unsigned g_amask[NWORDS];              // invariant: zero at launch entry
__device__ unsigned g_tab[TABW];                  // 2 bits/node: batch0|batch1 active
__device__ float g_query[BB*DD];
__device__ int   g_h0[BB];
__device__ float g_zv[LL][DD];
__device__ int   g_zfl[LL];
__device__ int   g_b64;

__device__ __forceinline__ int clampi(int v, int hi) {
    return v < 0 ? 0 : (v >= hi ? hi - 1 : v);
}
// bit-interleave: bit i of x -> bit 2i
__device__ __forceinline__ unsigned ileave16(unsigned x) {
    x = (x | (x << 8)) & 0x00FF00FFu;
    x = (x | (x << 4)) & 0x0F0F0F0Fu;
    x = (x | (x << 2)) & 0x33333333u;
    x = (x | (x << 1)) & 0x55555555u;
    return x;
}

// ---------------------------------------------------------------------------
// Zero only the state that is dirty after a previous launch: g_x, g_xmask,
// g_tab, g_zfl. (g_agg / g_amask are zero-initialized at module load and the
// update kernel restores their zero-invariant every launch.)
__global__ void k_zero() {
    int i = blockIdx.x * blockDim.x + threadIdx.x;   // 6250*256 = 1,600,000
    ((float4*)g_x)[i] = make_float4(0.f, 0.f, 0.f, 0.f);
    if (i < NWORDS) g_xmask[i] = 0u;
    if (i < TABW)   g_tab[i]   = 0u;
    if (i < LL)     g_zfl[i]   = 0;
}

// ---------------------------------------------------------------------------
// One block, 192 threads:
//  - parallel batch-dtype detect (odd 32-bit words all zero <=> int64)
//  - boundary/query/h0 setup + seed xmask and activity table
//  - z_l = relu(LN(layer_b[l])) for every layer (the exact update an
//    all-zero row receives), plus per-layer nonzero flags.
__global__ void k_setup(const float* __restrict__ rel,
                        const void* __restrict__ batch,
                        const float* __restrict__ layer_b,
                        const float* __restrict__ ln_g,
                        const float* __restrict__ ln_b) {
    __shared__ int s_not64;
    __shared__ float sb[LL][DD];
    __shared__ float smv[LL][2];
    int t = threadIdx.x;                 // 0..191
    if (t == 0) s_not64 = 0;
    __syncthreads();
    const int* bw = (const int*)batch;
    if (t < (BATCH_ELEMS - 1) / 2) {     // 98 odd words 1,3,...,195  (+197 below)
        if (bw[2*t + 1] != 0) atomicOr(&s_not64, 1);
    }
    if (t == 98 && bw[197] != 0) atomicOr(&s_not64, 1);
    __syncthreads();
    int is64 = !s_not64;
    if (t == 0) g_b64 = is64;

    if (t < DD) {
        int d = t;
        for (int b = 0; b < BB; b++) {
            int i0 = (b*KK + 0)*3;
            int h0 = clampi(is64 ? (int)((const long long*)batch)[i0    ] : bw[i0    ], NN);
            int r0 = clampi(is64 ? (int)((const long long*)batch)[i0 + 2] : bw[i0 + 2], RR);
            float q = rel[((size_t)b*RR + r0)*DD + d];
            g_query[b*DD + d] = q;
            g_x[((size_t)(b*NN + h0))*DD + d] = q;
            if (d == 0) {
                g_h0[b] = h0;
                int row = b*NN + h0;
                atomicOr(&g_xmask[row >> 5], 1u << (row & 31));
                atomicOr(&g_tab[h0 >> 4], 1u << (((h0 & 15) << 1) + b));
            }
        }
    }

    // z_l for all layers: thread t = l*64 + d
    int l = t >> 6, d = t & 63;
    float v = layer_b[l*DD + d];
    sb[l][d] = v;
    __syncthreads();
    if (d == 0) {
        float su = 0.f, sq = 0.f;
        for (int i = 0; i < DD; i++) { su += sb[l][i]; sq += sb[l][i]*sb[l][i]; }
        float mu = su * (1.f/DD);
        smv[l][0] = mu;
        smv[l][1] = sq * (1.f/DD) - mu*mu;
    }
    __syncthreads();
    float z = (v - smv[l][0]) * rsqrtf(smv[l][1] + 1e-5f) * ln_g[l*DD + d] + ln_b[l*DD + d];
    z = fmaxf(z, 0.f);
    g_zv[l][d] = z;
    if (z != 0.f) atomicOr(&g_zfl[l], 1);
}

// ---------------------------------------------------------------------------
// Message + scatter:  agg[b,dst] += x[b,src] * rel[b,etype].
// 4 edges per thread (int4 src load) + single packed-table probe per edge.
__global__ void k_scatter(const int* __restrict__ edge_index,
                          const int* __restrict__ etype,
                          const float* __restrict__ rel) {
    int idx  = blockIdx.x * blockDim.x + threadIdx.x;
    int lane = threadIdx.x & 31;
    int base = idx * 4;
    int4 s4 = make_int4(0, 0, 0, 0);
    unsigned pr0 = 0, pr1 = 0, pr2 = 0, pr3 = 0;
    if (base < EE) {
        s4 = ((const int4*)edge_index)[idx];
        pr0 = (g_tab[s4.x >> 4] >> ((s4.x & 15) << 1)) & 3u;
        pr1 = (g_tab[s4.y >> 4] >> ((s4.y & 15) << 1)) & 3u;
        pr2 = (g_tab[s4.z >> 4] >> ((s4.z & 15) << 1)) & 3u;
        pr3 = (g_tab[s4.w >> 4] >> ((s4.w & 15) << 1)) & 3u;
    }
    int srcs[4] = {s4.x, s4.y, s4.z, s4.w};
    unsigned prs[4] = {pr0, pr1, pr2, pr3};
    #pragma unroll
    for (int k = 0; k < 4; k++) {
        unsigned b0 = __ballot_sync(0xffffffffu, prs[k] & 1u);
        unsigned b1 = __ballot_sync(0xffffffffu, prs[k] & 2u);
        unsigned act = b0 | b1;
        while (act) {
            int j = __ffs(act) - 1;
            act &= act - 1;
            int ej = __shfl_sync(0xffffffffu, base, j) + k;
            int sj = __shfl_sync(0xffffffffu, srcs[k], j);
            int dj = 0, tj = 0;
            if (lane == j) { dj = edge_index[EE + ej]; tj = etype[ej]; }
            dj = __shfl_sync(0xffffffffu, dj, j);
            tj = __shfl_sync(0xffffffffu, tj, j);
            #pragma unroll
            for (int b = 0; b < BB; b++) {
                unsigned bb = b ? b1 : b0;
                if (!((bb >> j) & 1)) continue;      // uniform across warp
                float2 xv = ((const float2*)g_x)[((size_t)(b*NN + sj))*32 + lane];
                float2 rv = ((const float2*)rel)[((size_t)(b*RR + tj))*32 + lane];
                float* ap = &g_agg[((size_t)(b*NN + dj))*DD + 2*lane];
                atomicAdd(ap,     xv.x * rv.x);
                atomicAdd(ap + 1, xv.y * rv.y);
                if (lane == 0) {
                    int row = b*NN + dj;
                    atomicOr(&g_amask[row >> 5], 1u << (row & 31));
                }
            }
        }
    }
}

// ---------------------------------------------------------------------------
// Per-row update: upd = relu(LN([agg+boundary, x] @ W_l + b_l)); x += upd.
// One warp per 32-row mask word; processes only active rows; re-zeroes the
// agg rows it consumed and clears its amask word (zero-invariant restore).
__global__ void k_update(const float* __restrict__ W,
                         const float* __restrict__ bl,
                         const float* __restrict__ gg,
                         const float* __restrict__ beta, int l) {
    int wid  = (blockIdx.x * blockDim.x + threadIdx.x) >> 5;
    int lane = threadIdx.x & 31;
    if (wid >= NWORDS) return;
    unsigned xm = g_xmask[wid];
    unsigned am = g_amask[wid];
    unsigned act = xm | am;
    if (act) {
        const float* Wl = W + (size_t)l * 2 * DD * DD;
        float bj0  = bl[l*DD + 2*lane],   bj1  = bl[l*DD + 2*lane + 1];
        float gj0  = gg[l*DD + 2*lane],   gj1  = gg[l*DD + 2*lane + 1];
        float btj0 = beta[l*DD + 2*lane], btj1 = beta[l*DD + 2*lane + 1];
        unsigned rem = act;
        while (rem) {
            int jb = __ffs(rem) - 1;
            rem &= rem - 1;
            int row = wid * 32 + jb;
            int b   = row / NN;
            int n   = row - b * NN;
            float2 a2 = ((float2*)g_agg)[(size_t)row*32 + lane];
            float2 x2 = ((float2*)g_x)[(size_t)row*32 + lane];
            if (n == g_h0[b]) {
                a2.x += g_query[b*DD + 2*lane];
                a2.y += g_query[b*DD + 2*lane + 1];
            }
            float acc0 = bj0, acc1 = bj1;
            #pragma unroll 8
            for (int ii = 0; ii < 32; ii++) {       // cat[0:64] = agg
                float cx = __shfl_sync(0xffffffffu, a2.x, ii);
                float cy = __shfl_sync(0xffffffffu, a2.y, ii);
                float2 w0 = ((const float2*)(Wl + (2*ii    )*DD))[lane];
                float2 w1 = ((const float2*)(Wl + (2*ii + 1)*DD))[lane];
                acc0 += cx*w0.x + cy*w1.x;
                acc1 += cx*w0.y + cy*w1.y;
            }
            #pragma unroll 8
            for (int ii = 0; ii < 32; ii++) {       // cat[64:128] = x
                float cx = __shfl_sync(0xffffffffu, x2.x, ii);
                float cy = __shfl_sync(0xffffffffu, x2.y, ii);
                float2 w0 = ((const float2*)(Wl + (64 + 2*ii    )*DD))[lane];
                float2 w1 = ((const float2*)(Wl + (64 + 2*ii + 1)*DD))[lane];
                acc0 += cx*w0.x + cy*w1.x;
                acc1 += cx*w0.y + cy*w1.y;
            }
            float su = acc0 + acc1;
            float sq = acc0*acc0 + acc1*acc1;
            #pragma unroll
            for (int o = 16; o; o >>= 1) {
                su += __shfl_xor_sync(0xffffffffu, su, o);
                sq += __shfl_xor_sync(0xffffffffu, sq, o);
            }
            float mu  = su * (1.f/DD);
            float var = sq * (1.f/DD) - mu*mu;
            float rs  = rsqrtf(var + 1e-5f);
            float u0 = fmaxf((acc0 - mu)*rs*gj0 + btj0, 0.f);
            float u1 = fmaxf((acc1 - mu)*rs*gj1 + btj1, 0.f);
            x2.x += u0; x2.y += u1;
            ((float2*)g_x)[(size_t)row*32 + lane] = x2;
            ((float2*)g_agg)[(size_t)row*32 + lane] = make_float2(0.f, 0.f);
        }
        if (lane == 0) g_xmask[wid] = act;
    }
    if (lane == 0) g_amask[wid] = 0u;
}

// ---------------------------------------------------------------------------
// Fused: (a) rebuild the 2-bit activity table from xmask (Morton interleave
// of two 16-bit half-words; NN = 50000 == 16 mod 32 makes batch1 rows also
// 16-aligned), (b) if z_l != 0 (never for these inputs), densify: every
// still-zero row gets x += z_l and becomes active.
__global__ void k_fixtab(int l) {
    int r  = blockIdx.x * blockDim.x + threadIdx.x;
    int zf = g_zfl[l];
    if (r < TABW) {
        unsigned w;
        if (zf) {
            w = 0xFFFFFFFFu;
        } else {
            unsigned h0bits = (g_xmask[r >> 1] >> ((r & 1) * 16)) & 0xFFFFu;
            int row1 = NN + 16 * r;                 // 16-aligned within its word
            unsigned h1bits = (g_xmask[row1 >> 5] >> (row1 & 31)) & 0xFFFFu;
            w = ileave16(h0bits) | (ileave16(h1bits) << 1);
        }
        g_tab[r] = w;
    }
    if (zf) {
        if (r < NROWS && !((g_xmask[r >> 5] >> (r & 31)) & 1)) {
            for (int d = 0; d < DD; d++) g_x[(size_t)r*DD + d] += g_zv[l][d];
            atomicOr(&g_xmask[r >> 5], 1u << (r & 31));
        }
    }
}

// ---------------------------------------------------------------------------
// Final MLP scoring over the (b,k) query tails.
__global__ void k_score(const void* __restrict__ batch,
                        const float* __restrict__ w1,
                        const float* __restrict__ b1,
                        const float* __restrict__ w2,
                        const float* __restrict__ b2,
                        float* __restrict__ out) {
    __shared__ float feat[2*DD];
    __shared__ float hs[DD];
    int bk = blockIdx.x;            // 0..65
    int b = bk / KK, k = bk % KK;
    int j = threadIdx.x;            // 64
    int ti = (b*KK + k)*3 + 1;
    int t = clampi(g_b64 ? (int)((const long long*)batch)[ti]
                         : ((const int*)batch)[ti], NN);
    feat[j]      = g_x[((size_t)(b*NN + t))*DD + j];
    feat[DD + j] = g_query[b*DD + j];
    __syncthreads();
    float acc = b1[j];
    #pragma unroll 8
    for (int i = 0; i < 2*DD; i++) acc += feat[i] * w1[i*DD + j];
    float h = fmaxf(acc, 0.f);
    hs[j] = h * w2[j];
    __syncthreads();
    if (j == 0) {
        float s = b2[0];
        for (int i = 0; i < DD; i++) s += hs[i];
        out[b*KK + k] = s;
    }
}

// ---------------------------------------------------------------------------
extern "C" void kernel_launch(void* const* d_in, const int* in_sizes, int n_in,
                              void* d_out, int out_size) {
    const float* rel      = (const float*)d_in[0];
    const float* layer_w  = (const float*)d_in[1];
    const float* layer_b  = (const float*)d_in[2];
    const float* ln_g     = (const float*)d_in[3];
    const float* ln_b     = (const float*)d_in[4];
    const float* mlp_w1   = (const float*)d_in[5];
    const float* mlp_b1   = (const float*)d_in[6];
    const float* mlp_w2   = (const float*)d_in[7];
    const float* mlp_b2   = (const float*)d_in[8];
    const void*  batch    = d_in[9];
    const int*   edge_idx = (const int*)d_in[10];
    const int*   edge_typ = (const int*)d_in[11];
    float*       out      = (float*)d_out;

    k_zero<<<6250, 256>>>();
    k_setup<<<1, 192>>>(rel, batch, layer_b, ln_g, ln_b);
    for (int l = 0; l < LL; l++) {
        k_scatter<<<(EE/4 + 255)/256, 256>>>(edge_idx, edge_typ, rel);
        k_update<<<(NWORDS*32 + 255)/256, 256>>>(layer_w, layer_b, ln_g, ln_b, l);
        if (l < LL - 1) k_fixtab<<<(NROWS + 255)/256, 256>>>(l);
        else            k_fixtab<<<(NROWS + 255)/256, 256>>>(l);  // fixup still needed for z path
    }
    k_score<<<66, 64>>>(batch, mlp_w1, mlp_b1, mlp_w2, mlp_b2, out);
}

// round 7
// speedup vs baseline: 1.2939x; 1.2107x over previous
#include <cuda_runtime.h>

#define BB 2
#define KK 33
#define NN 50000
#define EE 800000
#define RR 200
#define DD 64
#define LL 3
#define NROWS (BB*NN)          /* 100000 */
#define NWORDS (NROWS/32)      /* 3125, exact */
#define TABW (NN*2/32)         /* 3125: 2 activity bits per node */
#define BATCH_ELEMS (BB*KK*3)  /* 198 */
#define UPD_BLOCKS 512
#define UPD_WARPS (UPD_BLOCKS*8)

__device__ __align__(16) float g_x[NROWS*DD];
__device__ __align__(16) float g_agg[NROWS*DD];   // invariant: zero at launch entry
__device__ unsigned g_xmask[NWORDS];              // invariant: reflects nonzero x rows
__device__ unsigned g_amask[NWORDS];              // invariant: zero at launch entry
__device__ unsigned g_tab[TABW];                  // 2 bits/node: batch0|batch1 active
__device__ int      g_worklist[NROWS];
__device__ int      g_nwork[LL];
__device__ float g_query[BB*DD];
__device__ int   g_h0[BB];
__device__ float g_zv[LL][DD];
__device__ int   g_zfl[LL];
__device__ int   g_b64;

__device__ __forceinline__ int clampi(int v, int hi) {
    return v < 0 ? 0 : (v >= hi ? hi - 1 : v);
}
// bit-interleave: bit i of x -> bit 2i
__device__ __forceinline__ unsigned ileave16(unsigned x) {
    x = (x | (x << 8)) & 0x00FF00FFu;
    x = (x | (x << 4)) & 0x0F0F0F0Fu;
    x = (x | (x << 2)) & 0x33333333u;
    x = (x | (x << 1)) & 0x55555555u;
    return x;
}

// ---------------------------------------------------------------------------
// Sparse re-zero: the entry xmask (left over from the previous replay, or
// all-zero on the very first run) marks exactly the dirty g_x rows. Warp per
// word zeroes only those rows, then clears its mask/tab words.
__global__ void k_zero() {
    int gid  = blockIdx.x * blockDim.x + threadIdx.x;
    int wid  = gid >> 5, lane = gid & 31;
    if (wid < NWORDS) {
        unsigned m = g_xmask[wid];
        while (m) {
            int j = __ffs(m) - 1;
            m &= m - 1;
            int row = wid * 32 + j;
            ((float2*)g_x)[(size_t)row*32 + lane] = make_float2(0.f, 0.f);
        }
        if (lane == 0) { g_xmask[wid] = 0u; g_tab[wid] = 0u; }
    }
    if (gid < LL) { g_zfl[gid] = 0; g_nwork[gid] = 0; }
}

// ---------------------------------------------------------------------------
// One block, 192 threads: batch-dtype detect, boundary/query/h0 setup,
// z_l = relu(LN(layer_b[l])) for every layer.
__global__ void k_setup(const float* __restrict__ rel,
                        const void* __restrict__ batch,
                        const float* __restrict__ layer_b,
                        const float* __restrict__ ln_g,
                        const float* __restrict__ ln_b) {
    __shared__ int s_not64;
    __shared__ float sb[LL][DD];
    __shared__ float smv[LL][2];
    int t = threadIdx.x;                 // 0..191
    if (t == 0) s_not64 = 0;
    __syncthreads();
    const int* bw = (const int*)batch;
    if (t < (BATCH_ELEMS - 1) / 2) {     // odd words 1,3,...,195
        if (bw[2*t + 1] != 0) atomicOr(&s_not64, 1);
    }
    if (t == 98 && bw[197] != 0) atomicOr(&s_not64, 1);
    __syncthreads();
    int is64 = !s_not64;
    if (t == 0) g_b64 = is64;

    if (t < DD) {
        int d = t;
        for (int b = 0; b < BB; b++) {
            int i0 = (b*KK + 0)*3;
            int h0 = clampi(is64 ? (int)((const long long*)batch)[i0    ] : bw[i0    ], NN);
            int r0 = clampi(is64 ? (int)((const long long*)batch)[i0 + 2] : bw[i0 + 2], RR);
            float q = rel[((size_t)b*RR + r0)*DD + d];
            g_query[b*DD + d] = q;
            g_x[((size_t)(b*NN + h0))*DD + d] = q;
            if (d == 0) {
                g_h0[b] = h0;
                int row = b*NN + h0;
                atomicOr(&g_xmask[row >> 5], 1u << (row & 31));
                atomicOr(&g_tab[h0 >> 4], 1u << (((h0 & 15) << 1) + b));
            }
        }
    }

    int l = t >> 6, d = t & 63;          // z_l for all layers
    float v = layer_b[l*DD + d];
    sb[l][d] = v;
    __syncthreads();
    if (d == 0) {
        float su = 0.f, sq = 0.f;
        for (int i = 0; i < DD; i++) { su += sb[l][i]; sq += sb[l][i]*sb[l][i]; }
        float mu = su * (1.f/DD);
        smv[l][0] = mu;
        smv[l][1] = sq * (1.f/DD) - mu*mu;
    }
    __syncthreads();
    float z = (v - smv[l][0]) * rsqrtf(smv[l][1] + 1e-5f) * ln_g[l*DD + d] + ln_b[l*DD + d];
    z = fmaxf(z, 0.f);
    g_zv[l][d] = z;
    if (z != 0.f) atomicOr(&g_zfl[l], 1);
}

// ---------------------------------------------------------------------------
// Message + scatter:  agg[b,dst] += x[b,src] * rel[b,etype].
// 4 edges per thread (int4 src load) + single packed-table probe per edge.
__global__ void k_scatter(const int* __restrict__ edge_index,
                          const int* __restrict__ etype,
                          const float* __restrict__ rel) {
    int idx  = blockIdx.x * blockDim.x + threadIdx.x;
    int lane = threadIdx.x & 31;
    int base = idx * 4;
    int4 s4 = make_int4(0, 0, 0, 0);
    unsigned pr0 = 0, pr1 = 0, pr2 = 0, pr3 = 0;
    if (base < EE) {
        s4 = ((const int4*)edge_index)[idx];
        pr0 = (g_tab[s4.x >> 4] >> ((s4.x & 15) << 1)) & 3u;
        pr1 = (g_tab[s4.y >> 4] >> ((s4.y & 15) << 1)) & 3u;
        pr2 = (g_tab[s4.z >> 4] >> ((s4.z & 15) << 1)) & 3u;
        pr3 = (g_tab[s4.w >> 4] >> ((s4.w & 15) << 1)) & 3u;
    }
    int srcs[4] = {s4.x, s4.y, s4.z, s4.w};
    unsigned prs[4] = {pr0, pr1, pr2, pr3};
    #pragma unroll
    for (int k = 0; k < 4; k++) {
        unsigned b0 = __ballot_sync(0xffffffffu, prs[k] & 1u);
        unsigned b1 = __ballot_sync(0xffffffffu, prs[k] & 2u);
        unsigned act = b0 | b1;
        while (act) {
            int j = __ffs(act) - 1;
            act &= act - 1;
            int ej = __shfl_sync(0xffffffffu, base, j) + k;
            int sj = __shfl_sync(0xffffffffu, srcs[k], j);
            int dj = 0, tj = 0;
            if (lane == j) { dj = edge_index[EE + ej]; tj = etype[ej]; }
            dj = __shfl_sync(0xffffffffu, dj, j);
            tj = __shfl_sync(0xffffffffu, tj, j);
            #pragma unroll
            for (int b = 0; b < BB; b++) {
                unsigned bb = b ? b1 : b0;
                if (!((bb >> j) & 1)) continue;      // uniform across warp
                float2 xv = ((const float2*)g_x)[((size_t)(b*NN + sj))*32 + lane];
                float2 rv = ((const float2*)rel)[((size_t)(b*RR + tj))*32 + lane];
                float* ap = &g_agg[((size_t)(b*NN + dj))*DD + 2*lane];
                atomicAdd(ap,     xv.x * rv.x);
                atomicAdd(ap + 1, xv.y * rv.y);
                if (lane == 0) {
                    int row = b*NN + dj;
                    atomicOr(&g_amask[row >> 5], 1u << (row & 31));
                }
            }
        }
    }
}

// ---------------------------------------------------------------------------
// Compact active rows (xmask|amask) into a worklist; merge masks; restore
// the amask zero-invariant.
__global__ void k_compact(int l) {
    int w = blockIdx.x * blockDim.x + threadIdx.x;
    if (w >= NWORDS) return;
    unsigned xm = g_xmask[w];
    unsigned am = g_amask[w];
    unsigned act = xm | am;
    if (am) g_amask[w] = 0u;
    if (act) {
        if (act != xm) g_xmask[w] = act;
        int n = __popc(act);
        int base = atomicAdd(&g_nwork[l], n);
        while (act) {
            int j = __ffs(act) - 1;
            act &= act - 1;
            g_worklist[base++] = w * 32 + j;
        }
    }
}

// ---------------------------------------------------------------------------
// Row-parallel update: one warp per worklist row,
// upd = relu(LN([agg+boundary, x] @ W_l + b_l)); x += upd; agg row re-zeroed.
__global__ void k_update(const float* __restrict__ W,
                         const float* __restrict__ bl,
                         const float* __restrict__ gg,
                         const float* __restrict__ beta, int l) {
    int gw   = (blockIdx.x * blockDim.x + threadIdx.x) >> 5;
    int lane = threadIdx.x & 31;
    int cnt  = g_nwork[l];
    if (gw >= cnt) return;
    const float* Wl = W + (size_t)l * 2 * DD * DD;
    float bj0  = bl[l*DD + 2*lane],   bj1  = bl[l*DD + 2*lane + 1];
    float gj0  = gg[l*DD + 2*lane],   gj1  = gg[l*DD + 2*lane + 1];
    float btj0 = beta[l*DD + 2*lane], btj1 = beta[l*DD + 2*lane + 1];
    for (int i = gw; i < cnt; i += UPD_WARPS) {
        int row = g_worklist[i];
        int b   = row / NN;
        int n   = row - b * NN;
        float2 a2 = ((float2*)g_agg)[(size_t)row*32 + lane];
        float2 x2 = ((float2*)g_x)[(size_t)row*32 + lane];
        if (n == g_h0[b]) {
            a2.x += g_query[b*DD + 2*lane];
            a2.y += g_query[b*DD + 2*lane + 1];
        }
        float acc0 = bj0, acc1 = bj1;
        #pragma unroll 8
        for (int ii = 0; ii < 32; ii++) {       // cat[0:64] = agg
            float cx = __shfl_sync(0xffffffffu, a2.x, ii);
            float cy = __shfl_sync(0xffffffffu, a2.y, ii);
            float2 w0 = ((const float2*)(Wl + (2*ii    )*DD))[lane];
            float2 w1 = ((const float2*)(Wl + (2*ii + 1)*DD))[lane];
            acc0 += cx*w0.x + cy*w1.x;
            acc1 += cx*w0.y + cy*w1.y;
        }
        #pragma unroll 8
        for (int ii = 0; ii < 32; ii++) {       // cat[64:128] = x
            float cx = __shfl_sync(0xffffffffu, x2.x, ii);
            float cy = __shfl_sync(0xffffffffu, x2.y, ii);
            float2 w0 = ((const float2*)(Wl + (64 + 2*ii    )*DD))[lane];
            float2 w1 = ((const float2*)(Wl + (64 + 2*ii + 1)*DD))[lane];
            acc0 += cx*w0.x + cy*w1.x;
            acc1 += cx*w0.y + cy*w1.y;
        }
        float su = acc0 + acc1;
        float sq = acc0*acc0 + acc1*acc1;
        #pragma unroll
        for (int o = 16; o; o >>= 1) {
            su += __shfl_xor_sync(0xffffffffu, su, o);
            sq += __shfl_xor_sync(0xffffffffu, sq, o);
        }
        float mu  = su * (1.f/DD);
        float var = sq * (1.f/DD) - mu*mu;
        float rs  = rsqrtf(var + 1e-5f);
        float u0 = fmaxf((acc0 - mu)*rs*gj0 + btj0, 0.f);
        float u1 = fmaxf((acc1 - mu)*rs*gj1 + btj1, 0.f);
        x2.x += u0; x2.y += u1;
        ((float2*)g_x)[(size_t)row*32 + lane] = x2;
        ((float2*)g_agg)[(size_t)row*32 + lane] = make_float2(0.f, 0.f);
    }
}

// ---------------------------------------------------------------------------
// Between layers: (a) rebuild the 2-bit activity table from xmask (Morton
// interleave of 16-bit half-words; NN == 16 mod 32 keeps batch1 rows
// 16-aligned), (b) if z_l != 0 (never for these inputs), densify.
__global__ void k_fixtab(int l) {
    int r  = blockIdx.x * blockDim.x + threadIdx.x;
    int zf = g_zfl[l];
    if (r < TABW) {
        unsigned w;
        if (zf) {
            w = 0xFFFFFFFFu;
        } else {
            unsigned h0bits = (g_xmask[r >> 1] >> ((r & 1) * 16)) & 0xFFFFu;
            int row1 = NN + 16 * r;                 // 16-aligned within its word
            unsigned h1bits = (g_xmask[row1 >> 5] >> (row1 & 31)) & 0xFFFFu;
            w = ileave16(h0bits) | (ileave16(h1bits) << 1);
        }
        g_tab[r] = w;
    }
    if (zf) {
        if (r < NROWS && !((g_xmask[r >> 5] >> (r & 31)) & 1)) {
            for (int d = 0; d < DD; d++) g_x[(size_t)r*DD + d] += g_zv[l][d];
            atomicOr(&g_xmask[r >> 5], 1u << (r & 31));
        }
    }
}

// ---------------------------------------------------------------------------
// Final MLP scoring; handles the (theoretical) z_{L-1} densify inline:
// a row still inactive after the last update holds x = 0 and owes + z_{L-1}.
__global__ void k_score(const void* __restrict__ batch,
                        const float* __restrict__ w1,
                        const float* __restrict__ b1,
                        const float* __restrict__ w2,
                        const float* __restrict__ b2,
                        float* __restrict__ out) {
    __shared__ float feat[2*DD];
    __shared__ float hs[DD];
    int bk = blockIdx.x;            // 0..65
    int b = bk / KK, k = bk % KK;
    int j = threadIdx.x;            // 64
    int ti = (b*KK + k)*3 + 1;
    int t = clampi(g_b64 ? (int)((const long long*)batch)[ti]
                         : ((const int*)batch)[ti], NN);
    int row = b*NN + t;
    float f = g_x[(size_t)row*DD + j];
    if (g_zfl[LL-1] && !((g_xmask[row >> 5] >> (row & 31)) & 1))
        f += g_zv[LL-1][j];
    feat[j]      = f;
    feat[DD + j] = g_query[b*DD + j];
    __syncthreads();
    float acc = b1[j];
    #pragma unroll 8
    for (int i = 0; i < 2*DD; i++) acc += feat[i] * w1[i*DD + j];
    float h = fmaxf(acc, 0.f);
    hs[j] = h * w2[j];
    __syncthreads();
    if (j == 0) {
        float s = b2[0];
        for (int i = 0; i < DD; i++) s += hs[i];
        out[b*KK + k] = s;
    }
}

// ---------------------------------------------------------------------------
extern "C" void kernel_launch(void* const* d_in, const int* in_sizes, int n_in,
                              void* d_out, int out_size) {
    const float* rel      = (const float*)d_in[0];
    const float* layer_w  = (const float*)d_in[1];
    const float* layer_b  = (const float*)d_in[2];
    const float* ln_g     = (const float*)d_in[3];
    const float* ln_b     = (const float*)d_in[4];
    const float* mlp_w1   = (const float*)d_in[5];
    const float* mlp_b1   = (const float*)d_in[6];
    const float* mlp_w2   = (const float*)d_in[7];
    const float* mlp_b2   = (const float*)d_in[8];
    const void*  batch    = d_in[9];
    const int*   edge_idx = (const int*)d_in[10];
    const int*   edge_typ = (const int*)d_in[11];
    float*       out      = (float*)d_out;

    k_zero<<<(NWORDS*32 + 255)/256, 256>>>();
    k_setup<<<1, 192>>>(rel, batch, layer_b, ln_g, ln_b);
    for (int l = 0; l < LL; l++) {
        k_scatter<<<(EE/4 + 255)/256, 256>>>(edge_idx, edge_typ, rel);
        k_compact<<<(NWORDS + 255)/256, 256>>>(l);
        k_update<<<UPD_BLOCKS, 256>>>(layer_w, layer_b, ln_g, ln_b, l);
        if (l < LL - 1) k_fixtab<<<(NROWS + 255)/256, 256>>>(l);
    }
    k_score<<<66, 64>>>(batch, mlp_w1, mlp_b1, mlp_w2, mlp_b2, out);
}